// round 16
// baseline (speedup 1.0000x reference)
#include <cuda_runtime.h>
#include <cuda_bf16.h>
#include <cuda_fp8.h>
#include <cstddef>
#include <cstdint>

typedef unsigned long long ull;

#define H    1024
#define BB   8
#define SS   256
#define VV   32000
#define MALL (BB*SS)          // 2048
#define NB_RNN 128
#define NTILE 250             // logits n-tiles (32000/128)
// RNN smem: W 24x1028 | hs0 2x8x1028 | hs1 8x1028 | red 8x192
#define RNN_SMEM ((24*1028 + 16*1028 + 8*1028 + 8*192) * 4)   // 203520
#define FP8_SCALE   64.0f
#define FP8_INVSQ   (1.0f / 4096.0f)

// ------------------------- device scratch ----------------------------------
__device__ float g_pre0[MALL * H];
__device__ float g_M10[H * H];
__device__ float g_c1[H];
__device__ float g_b0[H];
__device__ float g_h0buf[2 * BB * H];
__device__ float g_h1buf[2 * BB * H];
__device__ float g_psum[(size_t)MALL * NTILE];
__device__ uint8_t g_E8[(size_t)VV * H];          // 32MB (e4m3, x64)
__device__ uint8_t g_Y8[MALL * H];                // 2MB  (e4m3, x64)
__device__ __nv_bfloat16 g_Xb[MALL * H];
__device__ __nv_bfloat16 g_Wib[2 * H * H];
__device__ __nv_bfloat16 g_Wo0Tb[H * H];
__device__ __nv_bfloat16 g_Wo1b[H * H];
__device__ __nv_bfloat16 g_HS1b[MALL * H];
__device__ volatile unsigned g_bar_gen;
__device__ unsigned g_bar_cnt;

// ------------------------- helpers -----------------------------------------
__device__ __forceinline__ ull ffma2(ull a, ull b, ull c) {
    ull d;
    asm("fma.rn.f32x2 %0, %1, %2, %3;" : "=l"(d) : "l"(a), "l"(b), "l"(c));
    return d;
}
__device__ __forceinline__ float2 unpack2(ull v) {
    float x, y;
    asm("mov.b64 {%0, %1}, %2;" : "=f"(x), "=f"(y) : "l"(v));
    return make_float2(x, y);
}
__device__ __forceinline__ float hsum2(ull a) {
    float2 p = unpack2(a);
    return p.x + p.y;
}
__device__ __forceinline__ uint32_t smem_u32(const void* p) {
    uint32_t a;
    asm("{ .reg .u64 t; cvta.to.shared.u64 t, %1; cvt.u32.u64 %0, t; }"
        : "=r"(a) : "l"(p));
    return a;
}
__device__ __forceinline__ void cpasync16(uint32_t dst, const void* src) {
    asm volatile("cp.async.cg.shared.global [%0], [%1], 16;"
                 :: "r"(dst), "l"(src));
}
__device__ __forceinline__ void ldmx4(uint32_t* r, uint32_t addr) {
    asm volatile("ldmatrix.sync.aligned.m8n8.x4.shared.b16 {%0,%1,%2,%3}, [%4];"
                 : "=r"(r[0]), "=r"(r[1]), "=r"(r[2]), "=r"(r[3]) : "r"(addr));
}
__device__ __forceinline__ void mma16816(float* d, const uint32_t* a, const uint32_t* b) {
    asm volatile(
        "mma.sync.aligned.m16n8k16.row.col.f32.bf16.bf16.f32 "
        "{%0,%1,%2,%3}, {%4,%5,%6,%7}, {%8,%9}, {%0,%1,%2,%3};"
        : "+f"(d[0]), "+f"(d[1]), "+f"(d[2]), "+f"(d[3])
        : "r"(a[0]), "r"(a[1]), "r"(a[2]), "r"(a[3]), "r"(b[0]), "r"(b[1]));
}
__device__ __forceinline__ void mma16832f8(float* d, const uint32_t* a, const uint32_t* b) {
    asm volatile(
        "mma.sync.aligned.m16n8k32.row.col.f32.e4m3.e4m3.f32 "
        "{%0,%1,%2,%3}, {%4,%5,%6,%7}, {%8,%9}, {%0,%1,%2,%3};"
        : "+f"(d[0]), "+f"(d[1]), "+f"(d[2]), "+f"(d[3])
        : "r"(a[0]), "r"(a[1]), "r"(a[2]), "r"(a[3]), "r"(b[0]), "r"(b[1]));
}
// fast exp on fma/alu pipes (|x| < ~80; rel err ~4e-5)
__device__ __forceinline__ float fexp(float x) {
    float km = fmaf(x, 1.4426950408889634f, 12582912.0f);
    int   ik = __float_as_int(km) - 0x4B400000;
    float kf = km - 12582912.0f;
    float f  = fmaf(kf, -0.6931471805599453f, x);
    float p  = fmaf(f, 0.041666668f, 0.16666667f);
    p = fmaf(p, f, 0.5f);
    p = fmaf(p, f, 1.0f);
    p = fmaf(p, f, 1.0f);
    return __int_as_float(__float_as_int(p) + (ik << 23));
}
__device__ __forceinline__ uint16_t to_fp8x2(float lo, float hi) {
    return (uint16_t)__nv_cvt_float2_to_fp8x2(make_float2(lo, hi),
                                              __NV_SATFINITE, __NV_E4M3);
}

// ------------------------- grid barrier (atomic counter, 1 poller/CTA) -----
__device__ __forceinline__ void grid_barrier() {
    __threadfence();
    __syncthreads();
    if (threadIdx.x == 0) {
        unsigned my = g_bar_gen;
        unsigned t = atomicAdd(&g_bar_cnt, 1u);
        if (t == NB_RNN - 1u) {
            g_bar_cnt = 0u;
            __threadfence();
            g_bar_gen = my + 1u;
        } else {
            while (g_bar_gen == my) { }
        }
        __threadfence();
    }
    __syncthreads();
}

// ------------------------- fused prep (launch #1) --------------------------
// [0,2048) gather | [2048,3072) transpose | [3072,3200) bias | [3200,4224) Wi
// [4224,4736) Wo1 | [4736,20736) E -> fp8
__global__ __launch_bounds__(256) void fused_prep(
    const int* __restrict__ tokens, const float* __restrict__ E,
    const float* __restrict__ Wi, const float* __restrict__ bi,
    const float* __restrict__ bh, const float* __restrict__ Wo,
    const float* __restrict__ bo)
{
    __shared__ float tbuf[32][33];
    const int bx = blockIdx.x, t = threadIdx.x;
    if (bx < 2048) {                       // gather -> g_Xb (bf16)
        int b = bx >> 8, tt = bx & 255;
        int tok = tokens[b * SS + tt];
        float4 v = __ldg((const float4*)(E + (size_t)tok * H) + t);
        __nv_bfloat162 lo = __float22bfloat162_rn(make_float2(v.x, v.y));
        __nv_bfloat162 hi = __float22bfloat162_rn(make_float2(v.z, v.w));
        uint2 u;
        u.x = *(uint32_t*)&lo; u.y = *(uint32_t*)&hi;
        ((uint2*)(g_Xb + (size_t)bx * H))[t] = u;
    } else if (bx < 3072) {                // Wo0 transpose -> g_Wo0Tb
        int id = bx - 2048;
        int bxt = (id & 31) * 32, byt = (id >> 5) * 32;
        int tx = t & 31, ty = t >> 5;
        for (int j = ty; j < 32; j += 8)
            tbuf[j][tx] = Wo[(size_t)(byt + j) * H + bxt + tx];
        __syncthreads();
        for (int j = ty; j < 32; j += 8)
            g_Wo0Tb[(size_t)(bxt + j) * H + byt + tx] = __float2bfloat16(tbuf[tx][j]);
    } else if (bx < 3200) {                // bias prep -> g_c1, g_b0
        int w = t >> 5, lane = t & 31;
        int r = (bx - 3072) * 8 + w;
        const float* Wi1r = Wi + (size_t)H * H + (size_t)r * H;
        float s = 0.f;
        for (int k = lane; k < H; k += 32) s += Wi1r[k] * bo[k];
        #pragma unroll
        for (int off = 16; off; off >>= 1) s += __shfl_xor_sync(0xffffffffu, s, off);
        if (lane == 0) {
            g_c1[r] = s + bi[H + r] + bh[H + r];
            g_b0[r] = bi[r] + bh[r];
        }
    } else if (bx < 4224) {                // conv Wi -> g_Wib
        int i = (bx - 3200) * 256 + t;
        const float4* p = (const float4*)Wi + (size_t)i * 2;
        float4 a = __ldg(p), b = __ldg(p + 1);
        __nv_bfloat162 r0 = __float22bfloat162_rn(make_float2(a.x, a.y));
        __nv_bfloat162 r1 = __float22bfloat162_rn(make_float2(a.z, a.w));
        __nv_bfloat162 r2 = __float22bfloat162_rn(make_float2(b.x, b.y));
        __nv_bfloat162 r3 = __float22bfloat162_rn(make_float2(b.z, b.w));
        uint4 u;
        u.x = *(uint32_t*)&r0; u.y = *(uint32_t*)&r1;
        u.z = *(uint32_t*)&r2; u.w = *(uint32_t*)&r3;
        ((uint4*)g_Wib)[i] = u;
    } else if (bx < 4736) {                // conv Wo1 -> g_Wo1b
        int i = (bx - 4224) * 256 + t;
        const float4* p = (const float4*)(Wo + (size_t)H * H) + (size_t)i * 2;
        float4 a = __ldg(p), b = __ldg(p + 1);
        __nv_bfloat162 r0 = __float22bfloat162_rn(make_float2(a.x, a.y));
        __nv_bfloat162 r1 = __float22bfloat162_rn(make_float2(a.z, a.w));
        __nv_bfloat162 r2 = __float22bfloat162_rn(make_float2(b.x, b.y));
        __nv_bfloat162 r3 = __float22bfloat162_rn(make_float2(b.z, b.w));
        uint4 u;
        u.x = *(uint32_t*)&r0; u.y = *(uint32_t*)&r1;
        u.z = *(uint32_t*)&r2; u.w = *(uint32_t*)&r3;
        ((uint4*)g_Wo1b)[i] = u;
    } else {                               // E -> fp8 (x64)
        size_t i = (size_t)(bx - 4736) * 256 + t;   // 8 elems per thread
        const float4* p = (const float4*)E + i * 2;
        float4 a = __ldg(p), b = __ldg(p + 1);
        uint16_t q0 = to_fp8x2(a.x * FP8_SCALE, a.y * FP8_SCALE);
        uint16_t q1 = to_fp8x2(a.z * FP8_SCALE, a.w * FP8_SCALE);
        uint16_t q2 = to_fp8x2(b.x * FP8_SCALE, b.y * FP8_SCALE);
        uint16_t q3 = to_fp8x2(b.z * FP8_SCALE, b.w * FP8_SCALE);
        uint2 u;
        u.x = (uint32_t)q0 | ((uint32_t)q1 << 16);
        u.y = (uint32_t)q2 | ((uint32_t)q3 << 16);
        ((uint2*)g_E8)[i] = u;
    }
}

// ------------------------- 128x128 bf16 mma GEMM body (2-stage) ------------
#define S_LPB   80
#define S_TILEB 10240
__device__ __forceinline__ void gemm128_body(
    const __nv_bfloat16* __restrict__ A,
    const __nv_bfloat16* __restrict__ B,
    const float* __restrict__ bias,
    float* __restrict__ Cf,
    uint8_t* __restrict__ C8,
    int K, int ldc, int bx, int by, char* smem)
{
    const uint32_t sb = smem_u32(smem);
    const int tid = threadIdx.x;
    const int m0 = bx * 128, n0 = by * 128;
    const int niter = K >> 5;

    const int lrow = tid >> 1, lhalf = (tid & 1) * 16;
    const __nv_bfloat16* Ag = A + (size_t)(m0 + lrow) * K + lhalf;
    const __nv_bfloat16* Bg = B + (size_t)(n0 + lrow) * K + lhalf;
    const uint32_t sdst = (uint32_t)lrow * S_LPB + (uint32_t)lhalf * 2;

    float acc[4][4][4];
    #pragma unroll
    for (int i = 0; i < 4; i++)
        #pragma unroll
        for (int j = 0; j < 4; j++)
            #pragma unroll
            for (int q = 0; q < 4; q++) acc[i][j][q] = 0.f;

    const int w = tid >> 5, lane = tid & 31;
    const int wm = (w >> 2) * 64, wn = (w & 3) * 32;
    const int a_row = wm + ((lane >> 3) & 1) * 8 + (lane & 7);
    const int a_col8 = ((lane >> 4) & 1) * 8;
    const int b_row = wn + ((lane >> 4) & 1) * 8 + (lane & 7);
    const int b_col8 = ((lane >> 3) & 1) * 8;

    {
        cpasync16(sb + sdst, Ag);
        cpasync16(sb + sdst + 16, Ag + 8);
        cpasync16(sb + 2 * S_TILEB + sdst, Bg);
        cpasync16(sb + 2 * S_TILEB + sdst + 16, Bg + 8);
        asm volatile("cp.async.commit_group;" ::: "memory");
    }

    for (int it = 0; it < niter; ++it) {
        if (it + 1 < niter) {
            const uint32_t bo = (uint32_t)((it + 1) & 1) * S_TILEB;
            const int ko = (it + 1) * 32;
            cpasync16(sb + bo + sdst, Ag + ko);
            cpasync16(sb + bo + sdst + 16, Ag + ko + 8);
            cpasync16(sb + 2 * S_TILEB + bo + sdst, Bg + ko);
            cpasync16(sb + 2 * S_TILEB + bo + sdst + 16, Bg + ko + 8);
            asm volatile("cp.async.commit_group;" ::: "memory");
            asm volatile("cp.async.wait_group 1;" ::: "memory");
        } else {
            asm volatile("cp.async.wait_group 0;" ::: "memory");
        }
        __syncthreads();

        const uint32_t sA = sb + (uint32_t)(it & 1) * S_TILEB;
        const uint32_t sB = sA + 2 * S_TILEB;
        #pragma unroll
        for (int ks = 0; ks < 2; ++ks) {
            uint32_t af[4][4], bf[4][2];
            #pragma unroll
            for (int mf = 0; mf < 4; ++mf)
                ldmx4(af[mf], sA + (uint32_t)(a_row + mf * 16) * S_LPB
                              + (uint32_t)(ks * 16 + a_col8) * 2);
            #pragma unroll
            for (int nf2 = 0; nf2 < 2; ++nf2) {
                uint32_t r[4];
                ldmx4(r, sB + (uint32_t)(b_row + nf2 * 16) * S_LPB
                         + (uint32_t)(ks * 16 + b_col8) * 2);
                bf[nf2 * 2][0] = r[0]; bf[nf2 * 2][1] = r[1];
                bf[nf2 * 2 + 1][0] = r[2]; bf[nf2 * 2 + 1][1] = r[3];
            }
            #pragma unroll
            for (int mf = 0; mf < 4; ++mf)
                #pragma unroll
                for (int nf = 0; nf < 4; ++nf)
                    mma16816(acc[mf][nf], af[mf], bf[nf]);
        }
        __syncthreads();
    }

    const int erow = lane >> 2, ecol = (lane & 3) * 2;
    #pragma unroll
    for (int mf = 0; mf < 4; ++mf) {
        #pragma unroll
        for (int nf = 0; nf < 4; ++nf) {
            const int col = wn + nf * 8 + ecol;
            float b0v = bias ? bias[n0 + col] : 0.f;
            float b1v = bias ? bias[n0 + col + 1] : 0.f;
            float v00 = acc[mf][nf][0] + b0v, v01 = acc[mf][nf][1] + b1v;
            float v10 = acc[mf][nf][2] + b0v, v11 = acc[mf][nf][3] + b1v;
            const size_t r0 = (size_t)(m0 + wm + mf * 16 + erow);
            if (C8) {
                *(uint16_t*)(C8 + r0 * ldc + n0 + col) =
                    to_fp8x2(v00 * FP8_SCALE, v01 * FP8_SCALE);
                *(uint16_t*)(C8 + (r0 + 8) * ldc + n0 + col) =
                    to_fp8x2(v10 * FP8_SCALE, v11 * FP8_SCALE);
            } else {
                *(float2*)(Cf + r0 * ldc + n0 + col) = make_float2(v00, v01);
                *(float2*)(Cf + (r0 + 8) * ldc + n0 + col) = make_float2(v10, v11);
            }
        }
    }
}

// merged pre0 + M10 (one wave, occ 2): bx<16 -> pre0, else M10
__global__ __launch_bounds__(256, 2) void aux_gemms() {
    __shared__ __align__(16) char smem[4 * S_TILEB];
    if (blockIdx.x < 16) {
        gemm128_body(g_Xb, g_Wib, g_b0, g_pre0, nullptr, H, H,
                     blockIdx.x, blockIdx.y, smem);
    } else {
        gemm128_body(g_Wib + (size_t)H * H, g_Wo0Tb, nullptr, g_M10, nullptr, H, H,
                     blockIdx.x - 16, blockIdx.y, smem);
    }
}

// Y8 = fp8(x64)(HS1 @ Wo1.T + bo1), 128 CTAs occ 2
__global__ __launch_bounds__(256, 2) void y_gemm(const float* __restrict__ bo1) {
    __shared__ __align__(16) char smem[4 * S_TILEB];
    gemm128_body(g_HS1b, g_Wo1b, bo1, nullptr, g_Y8, H, H,
                 blockIdx.x, blockIdx.y, smem);
}

// ------------------------- persistent RNN, skew k=2, cp.async staged -------
// Tick t: phase A -> hs0[t] (t<SS); phase B -> hs1[t-2] (2<=t<=SS+1).
// m1 = M10 @ hs0[t-2] uses the RETAINED hs0 buffer (staged last tick) and
// runs while this tick's cp.async staging (hs0[t-1], hs1[t-3]) is in flight.
__global__ __launch_bounds__(256, 1) void rnn_kernel(const float* __restrict__ Wh,
                                                     const float* __restrict__ pre0) {
    extern __shared__ float sm[];
    float* Wsh  = sm;                        // [24][1028]
    float* hs0b = sm + 24 * 1028;            // [2][8][1028] double buffer
    float* hs1  = hs0b + 16 * 1028;          // [8][1028]
    float* red  = hs1 + 8 * 1028;            // [8 warps][24 rows][8 b]
    const int tid = threadIdx.x;
    const int r0 = blockIdx.x * 8;

    // load 24 weight rows (Wh0 | M10 | Wh1)
    for (int idx = tid; idx < 24 * 256; idx += 256) {
        int j = idx >> 8, c = (idx & 255) * 4;
        const float* srow;
        if (j < 8)       srow = Wh + (size_t)(r0 + j) * H;
        else if (j < 16) srow = g_M10 + (size_t)(r0 + j - 8) * H;
        else             srow = Wh + (size_t)H * H + (size_t)(r0 + j - 16) * H;
        *(float4*)(Wsh + j * 1028 + c) = __ldg((const float4*)(srow + c));
    }
    if (tid < 128) {
        int slot = tid >> 6, b = (tid >> 3) & 7, r = tid & 7;
        g_h0buf[slot * (BB * H) + b * H + r0 + r] = 0.f;
        g_h1buf[slot * (BB * H) + b * H + r0 + r] = 0.f;
    }
    grid_barrier();

    const int lane = tid & 31, w = tid >> 5;
    const int b = lane & 7, rr = lane >> 3;
    const int hoff = b * 1028 + w * 128;
    const float* w00 = Wsh + (rr * 2) * 1028 + w * 128;
    const float* w01 = Wsh + (rr * 2 + 1) * 1028 + w * 128;
    const float* w10 = Wsh + (8 + rr * 2) * 1028 + w * 128;
    const float* w11 = Wsh + (9 + rr * 2) * 1028 + w * 128;
    const float* w20 = Wsh + (16 + rr * 2) * 1028 + w * 128;
    const float* w21 = Wsh + (17 + rr * 2) * 1028 + w * 128;
    const uint32_t sb_hs0 = smem_u32(hs0b), sb_hs1 = smem_u32(hs1);

    float c1v = 0.f;
    if (tid >= 64 && tid < 128) c1v = g_c1[r0 + ((tid - 64) >> 3)];

    for (int tick = 0; tick <= SS + 1; ++tick) {
        const int wsl = tick & 1, rsl = wsl ^ 1;
        const bool doA = (tick < SS), doB = (tick >= 2);

        // prefetch this tick's pre0 (phase A input)
        float pre0v = 0.f;
        if (tid < 64 && doA) {
            int row = tid >> 3, bb = tid & 7;
            pre0v = __ldg(pre0 + (size_t)(bb * SS + tick) * H + r0 + row);
        }

        // issue cp.async staging: hs0[t-1] -> hs0b[wsl], hs1[t-3] -> hs1
        // full 32KB per buffer: 2048 chunks x 16B, 8 chunks/thread/buffer
        {
            const float* gg0 = g_h0buf + rsl * (BB * H);
            const float* gg1 = g_h1buf + rsl * (BB * H);
            const uint32_t d0 = sb_hs0 + (uint32_t)wsl * (8 * 1028 * 4);
            #pragma unroll
            for (int j = 0; j < 8; ++j) {
                int c = tid + 256 * j;
                int row = c >> 8, off = (c & 255) * 4;
                cpasync16(d0 + (uint32_t)(row * 1028 + off) * 4, gg0 + row * H + off);
            }
            #pragma unroll
            for (int j = 0; j < 8; ++j) {
                int c = tid + 256 * j;
                int row = c >> 8, off = (c & 255) * 4;
                cpasync16(sb_hs1 + (uint32_t)(row * 1028 + off) * 4, gg1 + row * H + off);
            }
            asm volatile("cp.async.commit_group;" ::: "memory");
        }

        // m1 = M10 @ hs0[t-2] from RETAINED buffer (overlaps staging)
        ull a10 = 0, a11 = 0;
        {
            const float* hold = hs0b + rsl * (8 * 1028) + hoff;
            #pragma unroll 8
            for (int i = 0; i < 32; ++i) {
                ulonglong2 hv  = *(const ulonglong2*)(hold + i * 4);
                ulonglong2 v10 = *(const ulonglong2*)(w10 + i * 4);
                ulonglong2 v11 = *(const ulonglong2*)(w11 + i * 4);
                a10 = ffma2(v10.x, hv.x, a10); a10 = ffma2(v10.y, hv.y, a10);
                a11 = ffma2(v11.x, hv.x, a11); a11 = ffma2(v11.y, hv.y, a11);
            }
        }

        asm volatile("cp.async.wait_group 0;" ::: "memory");
        __syncthreads();

        // m0 = Wh0 @ hs0[t-1]; m2 = Wh1 @ hs1[t-3]
        ull a00 = 0, a01 = 0, a20 = 0, a21 = 0;
        {
            const float* hnew = hs0b + wsl * (8 * 1028) + hoff;
            const float* h1p  = hs1 + hoff;
            #pragma unroll 8
            for (int i = 0; i < 32; ++i) {
                ulonglong2 h0v = *(const ulonglong2*)(hnew + i * 4);
                ulonglong2 h1v = *(const ulonglong2*)(h1p + i * 4);
                ulonglong2 v00 = *(const ulonglong2*)(w00 + i * 4);
                ulonglong2 v01 = *(const ulonglong2*)(w01 + i * 4);
                ulonglong2 v20 = *(const ulonglong2*)(w20 + i * 4);
                ulonglong2 v21 = *(const ulonglong2*)(w21 + i * 4);
                a00 = ffma2(v00.x, h0v.x, a00); a00 = ffma2(v00.y, h0v.y, a00);
                a01 = ffma2(v01.x, h0v.x, a01); a01 = ffma2(v01.y, h0v.y, a01);
                a20 = ffma2(v20.x, h1v.x, a20); a20 = ffma2(v20.y, h1v.y, a20);
                a21 = ffma2(v21.x, h1v.x, a21); a21 = ffma2(v21.y, h1v.y, a21);
            }
        }

        red[w * 192 + (rr * 2) * 8 + b]      = hsum2(a00);
        red[w * 192 + (rr * 2 + 1) * 8 + b]  = hsum2(a01);
        red[w * 192 + (8 + rr * 2) * 8 + b]  = hsum2(a10);
        red[w * 192 + (9 + rr * 2) * 8 + b]  = hsum2(a11);
        red[w * 192 + (16 + rr * 2) * 8 + b] = hsum2(a20);
        red[w * 192 + (17 + rr * 2) * 8 + b] = hsum2(a21);
        __syncthreads();

        if (tid < 64) {
            if (doA) {
                int row = tid >> 3, bb = tid & 7;
                float s = 0.f;
                #pragma unroll
                for (int ww = 0; ww < 8; ++ww) s += red[ww * 192 + row * 8 + bb];
                float v = tanhf(pre0v + s);
                __stcg(&g_h0buf[wsl * (BB * H) + bb * H + r0 + row], v);
            }
        } else if (tid < 128) {
            if (doB) {
                int j = tid - 64, row = j >> 3, bb = j & 7;
                float s1 = 0.f, s2 = 0.f;
                #pragma unroll
                for (int ww = 0; ww < 8; ++ww) {
                    s1 += red[ww * 192 + (8 + row) * 8 + bb];
                    s2 += red[ww * 192 + (16 + row) * 8 + bb];
                }
                float v = tanhf(c1v + s1 + s2);
                __stcg(&g_h1buf[wsl * (BB * H) + bb * H + r0 + row], v);
                g_HS1b[(size_t)(bb * SS + tick - 2) * H + r0 + row] = __float2bfloat16(v);
            }
        }
        grid_barrier();
    }
}

// ------------------------- fp8 logits GEMM, 128x128, 2-stage, occ 2 --------
__global__ __launch_bounds__(256, 2) void gemm_fp8_logits(
    const uint8_t* __restrict__ A,
    const uint8_t* __restrict__ B,
    float* __restrict__ out)
{
    __shared__ __align__(16) char smem[4 * S_TILEB];   // A0 A1 B0 B1
    __shared__ float sred[4][128];
    const uint32_t sb = smem_u32(smem);
    const int tid = threadIdx.x;
    const int m0 = blockIdx.x * 128, n0 = blockIdx.y * 128;
    const int niter = H >> 6;     // 16 (64 fp8 per iter)

    const int lrow = tid >> 1, lhalf = (tid & 1) * 32;   // byte offsets
    const uint8_t* Ag = A + (size_t)(m0 + lrow) * H + lhalf;
    const uint8_t* Bg = B + (size_t)(n0 + lrow) * H + lhalf;
    const uint32_t sdst = (uint32_t)lrow * S_LPB + (uint32_t)lhalf;

    float acc[4][4][4];
    #pragma unroll
    for (int i = 0; i < 4; i++)
        #pragma unroll
        for (int j = 0; j < 4; j++)
            #pragma unroll
            for (int q = 0; q < 4; q++) acc[i][j][q] = 0.f;

    const int w = tid >> 5, lane = tid & 31;
    const int wm = (w >> 2) * 64, wn = (w & 3) * 32;
    const int a_row = wm + ((lane >> 3) & 1) * 8 + (lane & 7);
    const int a_col8 = ((lane >> 4) & 1) * 8;
    const int b_row = wn + ((lane >> 4) & 1) * 8 + (lane & 7);
    const int b_col8 = ((lane >> 3) & 1) * 8;

    {
        cpasync16(sb + sdst, Ag);
        cpasync16(sb + sdst + 16, Ag + 16);
        cpasync16(sb + 2 * S_TILEB + sdst, Bg);
        cpasync16(sb + 2 * S_TILEB + sdst + 16, Bg + 16);
        asm volatile("cp.async.commit_group;" ::: "memory");
    }

    for (int it = 0; it < niter; ++it) {
        if (it + 1 < niter) {
            const uint32_t bo = (uint32_t)((it + 1) & 1) * S_TILEB;
            const int ko = (it + 1) * 64;
            cpasync16(sb + bo + sdst, Ag + ko);
            cpasync16(sb + bo + sdst + 16, Ag + ko + 16);
            cpasync16(sb + 2 * S_TILEB + bo + sdst, Bg + ko);
            cpasync16(sb + 2 * S_TILEB + bo + sdst + 16, Bg + ko + 16);
            asm volatile("cp.async.commit_group;" ::: "memory");
            asm volatile("cp.async.wait_group 1;" ::: "memory");
        } else {
            asm volatile("cp.async.wait_group 0;" ::: "memory");
        }
        __syncthreads();

        const uint32_t sA = sb + (uint32_t)(it & 1) * S_TILEB;
        const uint32_t sB = sA + 2 * S_TILEB;
        #pragma unroll
        for (int ks = 0; ks < 2; ++ks) {
            uint32_t af[4][4], bf[4][2];
            #pragma unroll
            for (int mf = 0; mf < 4; ++mf)
                ldmx4(af[mf], sA + (uint32_t)(a_row + mf * 16) * S_LPB
                              + (uint32_t)(ks * 16 + a_col8) * 2);
            #pragma unroll
            for (int nf2 = 0; nf2 < 2; ++nf2) {
                uint32_t r[4];
                ldmx4(r, sB + (uint32_t)(b_row + nf2 * 16) * S_LPB
                         + (uint32_t)(ks * 16 + b_col8) * 2);
                bf[nf2 * 2][0] = r[0]; bf[nf2 * 2][1] = r[1];
                bf[nf2 * 2 + 1][0] = r[2]; bf[nf2 * 2 + 1][1] = r[3];
            }
            #pragma unroll
            for (int mf = 0; mf < 4; ++mf)
                #pragma unroll
                for (int nf = 0; nf < 4; ++nf)
                    mma16832f8(acc[mf][nf], af[mf], bf[nf]);
        }
        __syncthreads();
    }

    const int erow = lane >> 2, ecol = (lane & 3) * 2;
    #pragma unroll
    for (int mf = 0; mf < 4; ++mf) {
        float sA = 0.f, sB = 0.f;
        #pragma unroll
        for (int nf = 0; nf < 4; ++nf) {
            const int col = wn + nf * 8 + ecol;
            float e0 = fexp(acc[mf][nf][0] * FP8_INVSQ);
            float e1 = fexp(acc[mf][nf][1] * FP8_INVSQ);
            float e2 = fexp(acc[mf][nf][2] * FP8_INVSQ);
            float e3 = fexp(acc[mf][nf][3] * FP8_INVSQ);
            const size_t r0 = (size_t)(m0 + wm + mf * 16 + erow);
            *(float2*)(out + r0 * VV + n0 + col) = make_float2(e0, e1);
            *(float2*)(out + (r0 + 8) * VV + n0 + col) = make_float2(e2, e3);
            sA += e0 + e1;
            sB += e2 + e3;
        }
        sA += __shfl_xor_sync(0xffffffffu, sA, 1);
        sA += __shfl_xor_sync(0xffffffffu, sA, 2);
        sB += __shfl_xor_sync(0xffffffffu, sB, 1);
        sB += __shfl_xor_sync(0xffffffffu, sB, 2);
        if ((lane & 3) == 0) {
            sred[w & 3][wm + mf * 16 + erow] = sA;
            sred[w & 3][wm + mf * 16 + erow + 8] = sB;
        }
    }
    __syncthreads();
    if (tid < 128) {
        float s = sred[0][tid] + sred[1][tid] + sred[2][tid] + sred[3][tid];
        g_psum[(size_t)(m0 + tid) * NTILE + blockIdx.y] = s;
    }
}

// ------------------------- normalize (softmax finish) ----------------------
__global__ __launch_bounds__(256) void normalize_kernel(float* __restrict__ out) {
    __shared__ float sh[256];
    const int row = blockIdx.x, t = threadIdx.x;
    sh[t] = (t < NTILE) ? g_psum[(size_t)row * NTILE + t] : 0.f;
    __syncthreads();
    #pragma unroll
    for (int s = 128; s; s >>= 1) {
        if (t < s) sh[t] += sh[t + s];
        __syncthreads();
    }
    const float inv = 1.0f / sh[0];
    float4* o = (float4*)(out + (size_t)row * VV);
    for (int i = t; i < VV / 4; i += 256) {
        float4 v = o[i];
        v.x *= inv; v.y *= inv; v.z *= inv; v.w *= inv;
        o[i] = v;
    }
}

// ------------------------- launch ------------------------------------------
extern "C" void kernel_launch(void* const* d_in, const int* in_sizes, int n_in,
                              void* d_out, int out_size) {
    const int*   tokens = (const int*)d_in[0];
    const float* E  = (const float*)d_in[1];
    const float* Wi = (const float*)d_in[2];
    const float* bi = (const float*)d_in[3];
    const float* Wh = (const float*)d_in[4];
    const float* bh = (const float*)d_in[5];
    const float* Wo = (const float*)d_in[6];
    const float* bo = (const float*)d_in[7];
    float* out = (float*)d_out;

    cudaFuncSetAttribute(rnn_kernel, cudaFuncAttributeMaxDynamicSharedMemorySize, RNN_SMEM);

    static float *pPre0 = nullptr;
    static uint8_t *pE8, *pY8;
    if (!pPre0) {
        cudaGetSymbolAddress((void**)&pPre0, g_pre0);
        cudaGetSymbolAddress((void**)&pE8,   g_E8);
        cudaGetSymbolAddress((void**)&pY8,   g_Y8);
    }

    // 1: all prep (gather, transpose, biases, Wi/Wo1 bf16, E fp8)
    fused_prep<<<20736, 256>>>(tokens, E, Wi, bi, bh, Wo, bo);
    // 2: pre0 + M10 merged (192 CTAs, occ 2 -> one wave)
    aux_gemms<<<dim3(24, 8), 256>>>();
    // 3: recurrence, skew k=2, cp.async-staged, m1 overlapped with staging
    rnn_kernel<<<NB_RNN, 256, RNN_SMEM>>>(Wh, pPre0);
    // 4: Y8 = fp8(x64)(HS1 @ Wo1.T + bo1)
    y_gemm<<<dim3(16, 8), 256>>>(bo + H);
    // 5: out = exp((Y8 @ E8^T)/4096), psum partials
    gemm_fp8_logits<<<dim3(16, NTILE), 256>>>(pY8, pE8, out);
    // 6: normalize rows
    normalize_kernel<<<MALL, 256>>>(out);
}

// round 17
// speedup vs baseline: 1.0350x; 1.0350x over previous
#include <cuda_runtime.h>
#include <cuda_bf16.h>
#include <cuda_fp8.h>
#include <cstddef>
#include <cstdint>

typedef unsigned long long ull;

#define H    1024
#define BB   8
#define SS   256
#define VV   32000
#define MALL (BB*SS)          // 2048
#define NB_RNN 128
#define NTILE 250             // logits n-tiles (32000/128)
#define RNN_SMEM ((24*1028 + 16*1028 + 8*192) * 4)   // 170624
#define FP8_SCALE   64.0f
#define FP8_INVSQ   (1.0f / 4096.0f)

// ------------------------- device scratch ----------------------------------
__device__ float g_pre0[MALL * H];
__device__ float g_M10[H * H];
__device__ float g_c1[H];
__device__ float g_b0[H];
__device__ float g_h0buf[2 * BB * H];
__device__ float g_h1buf[2 * BB * H];
__device__ float g_psum[(size_t)MALL * NTILE];
__device__ uint8_t g_E8[(size_t)VV * H];          // 32MB (e4m3, x64)
__device__ uint8_t g_Y8[MALL * H];                // 2MB  (e4m3, x64)
__device__ __nv_bfloat16 g_Xb[MALL * H];
__device__ __nv_bfloat16 g_Wib[2 * H * H];
__device__ __nv_bfloat16 g_Wo0Tb[H * H];
__device__ __nv_bfloat16 g_Wo1b[H * H];
__device__ __nv_bfloat16 g_HS1b[MALL * H];
__device__ volatile unsigned g_bar_gen;
__device__ unsigned g_bar_cnt;

// ------------------------- helpers -----------------------------------------
__device__ __forceinline__ ull ffma2(ull a, ull b, ull c) {
    ull d;
    asm("fma.rn.f32x2 %0, %1, %2, %3;" : "=l"(d) : "l"(a), "l"(b), "l"(c));
    return d;
}
__device__ __forceinline__ float2 unpack2(ull v) {
    float x, y;
    asm("mov.b64 {%0, %1}, %2;" : "=f"(x), "=f"(y) : "l"(v));
    return make_float2(x, y);
}
__device__ __forceinline__ float hsum2(ull a) {
    float2 p = unpack2(a);
    return p.x + p.y;
}
__device__ __forceinline__ float4 ldcg4(const float* p) {
    float4 v;
    asm volatile("ld.global.cg.v4.f32 {%0,%1,%2,%3}, [%4];"
                 : "=f"(v.x), "=f"(v.y), "=f"(v.z), "=f"(v.w) : "l"(p));
    return v;
}
__device__ __forceinline__ uint32_t smem_u32(const void* p) {
    uint32_t a;
    asm("{ .reg .u64 t; cvta.to.shared.u64 t, %1; cvt.u32.u64 %0, t; }"
        : "=r"(a) : "l"(p));
    return a;
}
__device__ __forceinline__ void cpasync16(uint32_t dst, const void* src) {
    asm volatile("cp.async.cg.shared.global [%0], [%1], 16;"
                 :: "r"(dst), "l"(src));
}
__device__ __forceinline__ void ldmx4(uint32_t* r, uint32_t addr) {
    asm volatile("ldmatrix.sync.aligned.m8n8.x4.shared.b16 {%0,%1,%2,%3}, [%4];"
                 : "=r"(r[0]), "=r"(r[1]), "=r"(r[2]), "=r"(r[3]) : "r"(addr));
}
__device__ __forceinline__ void mma16816(float* d, const uint32_t* a, const uint32_t* b) {
    asm volatile(
        "mma.sync.aligned.m16n8k16.row.col.f32.bf16.bf16.f32 "
        "{%0,%1,%2,%3}, {%4,%5,%6,%7}, {%8,%9}, {%0,%1,%2,%3};"
        : "+f"(d[0]), "+f"(d[1]), "+f"(d[2]), "+f"(d[3])
        : "r"(a[0]), "r"(a[1]), "r"(a[2]), "r"(a[3]), "r"(b[0]), "r"(b[1]));
}
__device__ __forceinline__ void mma16832f8(float* d, const uint32_t* a, const uint32_t* b) {
    asm volatile(
        "mma.sync.aligned.m16n8k32.row.col.f32.e4m3.e4m3.f32 "
        "{%0,%1,%2,%3}, {%4,%5,%6,%7}, {%8,%9}, {%0,%1,%2,%3};"
        : "+f"(d[0]), "+f"(d[1]), "+f"(d[2]), "+f"(d[3])
        : "r"(a[0]), "r"(a[1]), "r"(a[2]), "r"(a[3]), "r"(b[0]), "r"(b[1]));
}
// fast exp on fma/alu pipes (|x| < ~80; rel err ~4e-5)
__device__ __forceinline__ float fexp(float x) {
    float km = fmaf(x, 1.4426950408889634f, 12582912.0f);
    int   ik = __float_as_int(km) - 0x4B400000;
    float kf = km - 12582912.0f;
    float f  = fmaf(kf, -0.6931471805599453f, x);
    float p  = fmaf(f, 0.041666668f, 0.16666667f);
    p = fmaf(p, f, 0.5f);
    p = fmaf(p, f, 1.0f);
    p = fmaf(p, f, 1.0f);
    return __int_as_float(__float_as_int(p) + (ik << 23));
}
__device__ __forceinline__ uint16_t to_fp8x2(float lo, float hi) {
    return (uint16_t)__nv_cvt_float2_to_fp8x2(make_float2(lo, hi),
                                              __NV_SATFINITE, __NV_E4M3);
}

// ------------------------- grid barrier (atomic counter, 1 poller/CTA) -----
__device__ __forceinline__ void grid_barrier() {
    __threadfence();
    __syncthreads();
    if (threadIdx.x == 0) {
        unsigned my = g_bar_gen;
        unsigned t = atomicAdd(&g_bar_cnt, 1u);
        if (t == NB_RNN - 1u) {
            g_bar_cnt = 0u;
            __threadfence();
            g_bar_gen = my + 1u;
        } else {
            while (g_bar_gen == my) { }
        }
        __threadfence();
    }
    __syncthreads();
}

// ------------------------- fused prep (launch #1) --------------------------
// [0,2048) gather | [2048,3072) transpose | [3072,3200) bias | [3200,4224) Wi
// [4224,4736) Wo1 | [4736,20736) E -> fp8
__global__ __launch_bounds__(256) void fused_prep(
    const int* __restrict__ tokens, const float* __restrict__ E,
    const float* __restrict__ Wi, const float* __restrict__ bi,
    const float* __restrict__ bh, const float* __restrict__ Wo,
    const float* __restrict__ bo)
{
    __shared__ float tbuf[32][33];
    const int bx = blockIdx.x, t = threadIdx.x;
    if (bx < 2048) {                       // gather -> g_Xb (bf16)
        int b = bx >> 8, tt = bx & 255;
        int tok = tokens[b * SS + tt];
        float4 v = __ldg((const float4*)(E + (size_t)tok * H) + t);
        __nv_bfloat162 lo = __float22bfloat162_rn(make_float2(v.x, v.y));
        __nv_bfloat162 hi = __float22bfloat162_rn(make_float2(v.z, v.w));
        uint2 u;
        u.x = *(uint32_t*)&lo; u.y = *(uint32_t*)&hi;
        ((uint2*)(g_Xb + (size_t)bx * H))[t] = u;
    } else if (bx < 3072) {                // Wo0 transpose -> g_Wo0Tb
        int id = bx - 2048;
        int bxt = (id & 31) * 32, byt = (id >> 5) * 32;
        int tx = t & 31, ty = t >> 5;
        for (int j = ty; j < 32; j += 8)
            tbuf[j][tx] = Wo[(size_t)(byt + j) * H + bxt + tx];
        __syncthreads();
        for (int j = ty; j < 32; j += 8)
            g_Wo0Tb[(size_t)(bxt + j) * H + byt + tx] = __float2bfloat16(tbuf[tx][j]);
    } else if (bx < 3200) {                // bias prep -> g_c1, g_b0
        int w = t >> 5, lane = t & 31;
        int r = (bx - 3072) * 8 + w;
        const float* Wi1r = Wi + (size_t)H * H + (size_t)r * H;
        float s = 0.f;
        for (int k = lane; k < H; k += 32) s += Wi1r[k] * bo[k];
        #pragma unroll
        for (int off = 16; off; off >>= 1) s += __shfl_xor_sync(0xffffffffu, s, off);
        if (lane == 0) {
            g_c1[r] = s + bi[H + r] + bh[H + r];
            g_b0[r] = bi[r] + bh[r];
        }
    } else if (bx < 4224) {                // conv Wi -> g_Wib
        int i = (bx - 3200) * 256 + t;
        const float4* p = (const float4*)Wi + (size_t)i * 2;
        float4 a = __ldg(p), b = __ldg(p + 1);
        __nv_bfloat162 r0 = __float22bfloat162_rn(make_float2(a.x, a.y));
        __nv_bfloat162 r1 = __float22bfloat162_rn(make_float2(a.z, a.w));
        __nv_bfloat162 r2 = __float22bfloat162_rn(make_float2(b.x, b.y));
        __nv_bfloat162 r3 = __float22bfloat162_rn(make_float2(b.z, b.w));
        uint4 u;
        u.x = *(uint32_t*)&r0; u.y = *(uint32_t*)&r1;
        u.z = *(uint32_t*)&r2; u.w = *(uint32_t*)&r3;
        ((uint4*)g_Wib)[i] = u;
    } else if (bx < 4736) {                // conv Wo1 -> g_Wo1b
        int i = (bx - 4224) * 256 + t;
        const float4* p = (const float4*)(Wo + (size_t)H * H) + (size_t)i * 2;
        float4 a = __ldg(p), b = __ldg(p + 1);
        __nv_bfloat162 r0 = __float22bfloat162_rn(make_float2(a.x, a.y));
        __nv_bfloat162 r1 = __float22bfloat162_rn(make_float2(a.z, a.w));
        __nv_bfloat162 r2 = __float22bfloat162_rn(make_float2(b.x, b.y));
        __nv_bfloat162 r3 = __float22bfloat162_rn(make_float2(b.z, b.w));
        uint4 u;
        u.x = *(uint32_t*)&r0; u.y = *(uint32_t*)&r1;
        u.z = *(uint32_t*)&r2; u.w = *(uint32_t*)&r3;
        ((uint4*)g_Wo1b)[i] = u;
    } else {                               // E -> fp8 (x64)
        size_t i = (size_t)(bx - 4736) * 256 + t;   // 8 elems per thread
        const float4* p = (const float4*)E + i * 2;
        float4 a = __ldg(p), b = __ldg(p + 1);
        uint16_t q0 = to_fp8x2(a.x * FP8_SCALE, a.y * FP8_SCALE);
        uint16_t q1 = to_fp8x2(a.z * FP8_SCALE, a.w * FP8_SCALE);
        uint16_t q2 = to_fp8x2(b.x * FP8_SCALE, b.y * FP8_SCALE);
        uint16_t q3 = to_fp8x2(b.z * FP8_SCALE, b.w * FP8_SCALE);
        uint2 u;
        u.x = (uint32_t)q0 | ((uint32_t)q1 << 16);
        u.y = (uint32_t)q2 | ((uint32_t)q3 << 16);
        ((uint2*)g_E8)[i] = u;
    }
}

// ------------------------- 128x128 bf16 mma GEMM body (2-stage) ------------
#define S_LPB   80
#define S_TILEB 10240
__device__ __forceinline__ void gemm128_body(
    const __nv_bfloat16* __restrict__ A,
    const __nv_bfloat16* __restrict__ B,
    const float* __restrict__ bias,
    float* __restrict__ Cf,
    uint8_t* __restrict__ C8,
    int K, int ldc, int bx, int by, char* smem)
{
    const uint32_t sb = smem_u32(smem);
    const int tid = threadIdx.x;
    const int m0 = bx * 128, n0 = by * 128;
    const int niter = K >> 5;

    const int lrow = tid >> 1, lhalf = (tid & 1) * 16;
    const __nv_bfloat16* Ag = A + (size_t)(m0 + lrow) * K + lhalf;
    const __nv_bfloat16* Bg = B + (size_t)(n0 + lrow) * K + lhalf;
    const uint32_t sdst = (uint32_t)lrow * S_LPB + (uint32_t)lhalf * 2;

    float acc[4][4][4];
    #pragma unroll
    for (int i = 0; i < 4; i++)
        #pragma unroll
        for (int j = 0; j < 4; j++)
            #pragma unroll
            for (int q = 0; q < 4; q++) acc[i][j][q] = 0.f;

    const int w = tid >> 5, lane = tid & 31;
    const int wm = (w >> 2) * 64, wn = (w & 3) * 32;
    const int a_row = wm + ((lane >> 3) & 1) * 8 + (lane & 7);
    const int a_col8 = ((lane >> 4) & 1) * 8;
    const int b_row = wn + ((lane >> 4) & 1) * 8 + (lane & 7);
    const int b_col8 = ((lane >> 3) & 1) * 8;

    {
        cpasync16(sb + sdst, Ag);
        cpasync16(sb + sdst + 16, Ag + 8);
        cpasync16(sb + 2 * S_TILEB + sdst, Bg);
        cpasync16(sb + 2 * S_TILEB + sdst + 16, Bg + 8);
        asm volatile("cp.async.commit_group;" ::: "memory");
    }

    for (int it = 0; it < niter; ++it) {
        if (it + 1 < niter) {
            const uint32_t bo = (uint32_t)((it + 1) & 1) * S_TILEB;
            const int ko = (it + 1) * 32;
            cpasync16(sb + bo + sdst, Ag + ko);
            cpasync16(sb + bo + sdst + 16, Ag + ko + 8);
            cpasync16(sb + 2 * S_TILEB + bo + sdst, Bg + ko);
            cpasync16(sb + 2 * S_TILEB + bo + sdst + 16, Bg + ko + 8);
            asm volatile("cp.async.commit_group;" ::: "memory");
            asm volatile("cp.async.wait_group 1;" ::: "memory");
        } else {
            asm volatile("cp.async.wait_group 0;" ::: "memory");
        }
        __syncthreads();

        const uint32_t sA = sb + (uint32_t)(it & 1) * S_TILEB;
        const uint32_t sB = sA + 2 * S_TILEB;
        #pragma unroll
        for (int ks = 0; ks < 2; ++ks) {
            uint32_t af[4][4], bf[4][2];
            #pragma unroll
            for (int mf = 0; mf < 4; ++mf)
                ldmx4(af[mf], sA + (uint32_t)(a_row + mf * 16) * S_LPB
                              + (uint32_t)(ks * 16 + a_col8) * 2);
            #pragma unroll
            for (int nf2 = 0; nf2 < 2; ++nf2) {
                uint32_t r[4];
                ldmx4(r, sB + (uint32_t)(b_row + nf2 * 16) * S_LPB
                         + (uint32_t)(ks * 16 + b_col8) * 2);
                bf[nf2 * 2][0] = r[0]; bf[nf2 * 2][1] = r[1];
                bf[nf2 * 2 + 1][0] = r[2]; bf[nf2 * 2 + 1][1] = r[3];
            }
            #pragma unroll
            for (int mf = 0; mf < 4; ++mf)
                #pragma unroll
                for (int nf = 0; nf < 4; ++nf)
                    mma16816(acc[mf][nf], af[mf], bf[nf]);
        }
        __syncthreads();
    }

    const int erow = lane >> 2, ecol = (lane & 3) * 2;
    #pragma unroll
    for (int mf = 0; mf < 4; ++mf) {
        #pragma unroll
        for (int nf = 0; nf < 4; ++nf) {
            const int col = wn + nf * 8 + ecol;
            float b0v = bias ? bias[n0 + col] : 0.f;
            float b1v = bias ? bias[n0 + col + 1] : 0.f;
            float v00 = acc[mf][nf][0] + b0v, v01 = acc[mf][nf][1] + b1v;
            float v10 = acc[mf][nf][2] + b0v, v11 = acc[mf][nf][3] + b1v;
            const size_t r0 = (size_t)(m0 + wm + mf * 16 + erow);
            if (C8) {
                *(uint16_t*)(C8 + r0 * ldc + n0 + col) =
                    to_fp8x2(v00 * FP8_SCALE, v01 * FP8_SCALE);
                *(uint16_t*)(C8 + (r0 + 8) * ldc + n0 + col) =
                    to_fp8x2(v10 * FP8_SCALE, v11 * FP8_SCALE);
            } else {
                *(float2*)(Cf + r0 * ldc + n0 + col) = make_float2(v00, v01);
                *(float2*)(Cf + (r0 + 8) * ldc + n0 + col) = make_float2(v10, v11);
            }
        }
    }
}

// merged pre0 + M10 (one wave, occ 2): bx<16 -> pre0, else M10
__global__ __launch_bounds__(256, 2) void aux_gemms() {
    __shared__ __align__(16) char smem[4 * S_TILEB];
    if (blockIdx.x < 16) {
        gemm128_body(g_Xb, g_Wib, g_b0, g_pre0, nullptr, H, H,
                     blockIdx.x, blockIdx.y, smem);
    } else {
        gemm128_body(g_Wib + (size_t)H * H, g_Wo0Tb, nullptr, g_M10, nullptr, H, H,
                     blockIdx.x - 16, blockIdx.y, smem);
    }
}

// Y8 = fp8(x64)(HS1 @ Wo1.T + bo1), 128 CTAs occ 2
__global__ __launch_bounds__(256, 2) void y_gemm(const float* __restrict__ bo1) {
    __shared__ __align__(16) char smem[4 * S_TILEB];
    gemm128_body(g_HS1b, g_Wo1b, bo1, nullptr, g_Y8, H, H,
                 blockIdx.x, blockIdx.y, smem);
}

// ------------------------- persistent skewed RNN (r14 structure) -----------
__global__ __launch_bounds__(256, 1) void rnn_kernel(const float* __restrict__ Wh,
                                                     const float* __restrict__ pre0) {
    extern __shared__ float sm[];
    float* Wsh = sm;                       // [24][1028]
    float* hs0 = sm + 24 * 1028;           // [8][1028]
    float* hs1 = hs0 + 8 * 1028;           // [8][1028]
    float* red = hs1 + 8 * 1028;           // [8 warps][24 rows][8 b]
    const int tid = threadIdx.x;
    const int r0 = blockIdx.x * 8;

    for (int idx = tid; idx < 24 * 256; idx += 256) {
        int j = idx >> 8, c = (idx & 255) * 4;
        const float* srow;
        if (j < 8)       srow = Wh + (size_t)(r0 + j) * H;
        else if (j < 16) srow = g_M10 + (size_t)(r0 + j - 8) * H;
        else             srow = Wh + (size_t)H * H + (size_t)(r0 + j - 16) * H;
        *(float4*)(Wsh + j * 1028 + c) = __ldg((const float4*)(srow + c));
    }
    if (tid < 128) {
        int slot = tid >> 6, b = (tid >> 3) & 7, r = tid & 7;
        g_h0buf[slot * (BB * H) + b * H + r0 + r] = 0.f;
        g_h1buf[slot * (BB * H) + b * H + r0 + r] = 0.f;
    }
    grid_barrier();

    const int lane = tid & 31, w = tid >> 5;
    const int b = lane & 7, rr = lane >> 3;
    const float* h0p = hs0 + b * 1028 + w * 128;
    const float* h1p = hs1 + b * 1028 + w * 128;
    const float* w00 = Wsh + (rr * 2) * 1028 + w * 128;
    const float* w01 = Wsh + (rr * 2 + 1) * 1028 + w * 128;
    const float* w10 = Wsh + (8 + rr * 2) * 1028 + w * 128;
    const float* w11 = Wsh + (9 + rr * 2) * 1028 + w * 128;
    const float* w20 = Wsh + (16 + rr * 2) * 1028 + w * 128;
    const float* w21 = Wsh + (17 + rr * 2) * 1028 + w * 128;

    float c1v = 0.f;
    if (tid >= 64 && tid < 128) c1v = g_c1[r0 + ((tid - 64) >> 3)];

    for (int tick = 0; tick <= SS; ++tick) {
        const int rs0 = (tick & 1) ^ 1, rs1 = (tick & 1);
        float pre0v = 0.f;
        if (tid < 64 && tick < SS) {
            int row = tid >> 3, bb = tid & 7;
            pre0v = __ldg(pre0 + (size_t)(bb * SS + tick) * H + r0 + row);
        }
        {
            const float* gg0 = g_h0buf + rs0 * (BB * H);
            const float* gg1 = g_h1buf + rs1 * (BB * H);
            for (int c = tid; c < 2048; c += 256) {
                int row = c >> 8, seg = (c & 255) * 4;
                *(float4*)(hs0 + row * 1028 + seg) = ldcg4(gg0 + row * H + seg);
                *(float4*)(hs1 + row * 1028 + seg) = ldcg4(gg1 + row * H + seg);
            }
        }
        __syncthreads();

        ull a00 = 0, a01 = 0, a10 = 0, a11 = 0, a20 = 0, a21 = 0;
        #pragma unroll 8
        for (int i = 0; i < 32; ++i) {
            ulonglong2 h0v = *(const ulonglong2*)(h0p + i * 4);
            ulonglong2 h1v = *(const ulonglong2*)(h1p + i * 4);
            ulonglong2 v00 = *(const ulonglong2*)(w00 + i * 4);
            ulonglong2 v01 = *(const ulonglong2*)(w01 + i * 4);
            ulonglong2 v10 = *(const ulonglong2*)(w10 + i * 4);
            ulonglong2 v11 = *(const ulonglong2*)(w11 + i * 4);
            ulonglong2 v20 = *(const ulonglong2*)(w20 + i * 4);
            ulonglong2 v21 = *(const ulonglong2*)(w21 + i * 4);
            a00 = ffma2(v00.x, h0v.x, a00); a00 = ffma2(v00.y, h0v.y, a00);
            a01 = ffma2(v01.x, h0v.x, a01); a01 = ffma2(v01.y, h0v.y, a01);
            a10 = ffma2(v10.x, h0v.x, a10); a10 = ffma2(v10.y, h0v.y, a10);
            a11 = ffma2(v11.x, h0v.x, a11); a11 = ffma2(v11.y, h0v.y, a11);
            a20 = ffma2(v20.x, h1v.x, a20); a20 = ffma2(v20.y, h1v.y, a20);
            a21 = ffma2(v21.x, h1v.x, a21); a21 = ffma2(v21.y, h1v.y, a21);
        }
        red[w * 192 + (rr * 2) * 8 + b]      = hsum2(a00);
        red[w * 192 + (rr * 2 + 1) * 8 + b]  = hsum2(a01);
        red[w * 192 + (8 + rr * 2) * 8 + b]  = hsum2(a10);
        red[w * 192 + (9 + rr * 2) * 8 + b]  = hsum2(a11);
        red[w * 192 + (16 + rr * 2) * 8 + b] = hsum2(a20);
        red[w * 192 + (17 + rr * 2) * 8 + b] = hsum2(a21);
        __syncthreads();

        if (tid < 64) {
            if (tick < SS) {
                int row = tid >> 3, bb = tid & 7;
                float s = 0.f;
                #pragma unroll
                for (int ww = 0; ww < 8; ++ww) s += red[ww * 192 + row * 8 + bb];
                float v = tanhf(pre0v + s);
                __stcg(&g_h0buf[rs1 * (BB * H) + bb * H + r0 + row], v);
            }
        } else if (tid < 128) {
            if (tick >= 1) {
                int j = tid - 64, row = j >> 3, bb = j & 7;
                float s1 = 0.f, s2 = 0.f;
                #pragma unroll
                for (int ww = 0; ww < 8; ++ww) {
                    s1 += red[ww * 192 + (8 + row) * 8 + bb];
                    s2 += red[ww * 192 + (16 + row) * 8 + bb];
                }
                float v = tanhf(c1v + s1 + s2);
                __stcg(&g_h1buf[rs0 * (BB * H) + bb * H + r0 + row], v);
                g_HS1b[(size_t)(bb * SS + tick - 1) * H + r0 + row] = __float2bfloat16(v);
            }
        }
        grid_barrier();
    }
}

// ------------------------- fp8 logits GEMM, 128x128, 3-stage, occ 2 --------
// One __syncthreads per k-iter; uniform commit_group for exact wait counting.
#define L3_STG (2 * S_TILEB)   // A + B per stage = 20480
__global__ __launch_bounds__(256, 2) void gemm_fp8_logits(
    const uint8_t* __restrict__ A,
    const uint8_t* __restrict__ B,
    float* __restrict__ out)
{
    __shared__ __align__(16) char smem[3 * L3_STG];    // 61440
    __shared__ float sred[4][128];
    const uint32_t sb = smem_u32(smem);
    const int tid = threadIdx.x;
    const int m0 = blockIdx.x * 128, n0 = blockIdx.y * 128;
    const int niter = H >> 6;     // 16 (64 fp8 per iter)

    const int lrow = tid >> 1, lhalf = (tid & 1) * 32;   // byte offsets
    const uint8_t* Ag = A + (size_t)(m0 + lrow) * H + lhalf;
    const uint8_t* Bg = B + (size_t)(n0 + lrow) * H + lhalf;
    const uint32_t sdst = (uint32_t)lrow * S_LPB + (uint32_t)lhalf;

    float acc[4][4][4];
    #pragma unroll
    for (int i = 0; i < 4; i++)
        #pragma unroll
        for (int j = 0; j < 4; j++)
            #pragma unroll
            for (int q = 0; q < 4; q++) acc[i][j][q] = 0.f;

    const int w = tid >> 5, lane = tid & 31;
    const int wm = (w >> 2) * 64, wn = (w & 3) * 32;
    const int a_row = wm + ((lane >> 3) & 1) * 8 + (lane & 7);
    const int a_col8 = ((lane >> 4) & 1) * 8;
    const int b_row = wn + ((lane >> 4) & 1) * 8 + (lane & 7);
    const int b_col8 = ((lane >> 3) & 1) * 8;

    auto issue_stage = [&](int s, int ko) {
        const uint32_t sA = sb + (uint32_t)s * L3_STG;
        const uint32_t sB = sA + S_TILEB;
        cpasync16(sA + sdst, Ag + ko);
        cpasync16(sA + sdst + 16, Ag + ko + 16);
        cpasync16(sB + sdst, Bg + ko);
        cpasync16(sB + sdst + 16, Bg + ko + 16);
    };

    // prologue: stages 0, 1
    issue_stage(0, 0);
    asm volatile("cp.async.commit_group;" ::: "memory");
    issue_stage(1, 64);
    asm volatile("cp.async.commit_group;" ::: "memory");

    int stage = 0;
    for (int it = 0; it < niter; ++it) {
        asm volatile("cp.async.wait_group 1;" ::: "memory");
        __syncthreads();                         // one sync: read+write safety
        if (it + 2 < niter) {
            int s2 = stage + 2; if (s2 >= 3) s2 -= 3;
            issue_stage(s2, (it + 2) * 64);
        }
        asm volatile("cp.async.commit_group;" ::: "memory");

        const uint32_t sA = sb + (uint32_t)stage * L3_STG;
        const uint32_t sB = sA + S_TILEB;
        #pragma unroll
        for (int ks = 0; ks < 2; ++ks) {
            uint32_t af[4][4], bf[4][2];
            #pragma unroll
            for (int mf = 0; mf < 4; ++mf)
                ldmx4(af[mf], sA + (uint32_t)(a_row + mf * 16) * S_LPB
                              + (uint32_t)(ks * 16 + a_col8) * 2);
            #pragma unroll
            for (int nf2 = 0; nf2 < 2; ++nf2) {
                uint32_t r[4];
                ldmx4(r, sB + (uint32_t)(b_row + nf2 * 16) * S_LPB
                         + (uint32_t)(ks * 16 + b_col8) * 2);
                bf[nf2 * 2][0] = r[0]; bf[nf2 * 2][1] = r[1];
                bf[nf2 * 2 + 1][0] = r[2]; bf[nf2 * 2 + 1][1] = r[3];
            }
            #pragma unroll
            for (int mf = 0; mf < 4; ++mf)
                #pragma unroll
                for (int nf = 0; nf < 4; ++nf)
                    mma16832f8(acc[mf][nf], af[mf], bf[nf]);
        }
        if (++stage == 3) stage = 0;
    }
    __syncthreads();

    const int erow = lane >> 2, ecol = (lane & 3) * 2;
    #pragma unroll
    for (int mf = 0; mf < 4; ++mf) {
        float sA = 0.f, sB = 0.f;
        #pragma unroll
        for (int nf = 0; nf < 4; ++nf) {
            const int col = wn + nf * 8 + ecol;
            float e0 = fexp(acc[mf][nf][0] * FP8_INVSQ);
            float e1 = fexp(acc[mf][nf][1] * FP8_INVSQ);
            float e2 = fexp(acc[mf][nf][2] * FP8_INVSQ);
            float e3 = fexp(acc[mf][nf][3] * FP8_INVSQ);
            const size_t r0 = (size_t)(m0 + wm + mf * 16 + erow);
            *(float2*)(out + r0 * VV + n0 + col) = make_float2(e0, e1);
            *(float2*)(out + (r0 + 8) * VV + n0 + col) = make_float2(e2, e3);
            sA += e0 + e1;
            sB += e2 + e3;
        }
        sA += __shfl_xor_sync(0xffffffffu, sA, 1);
        sA += __shfl_xor_sync(0xffffffffu, sA, 2);
        sB += __shfl_xor_sync(0xffffffffu, sB, 1);
        sB += __shfl_xor_sync(0xffffffffu, sB, 2);
        if ((lane & 3) == 0) {
            sred[w & 3][wm + mf * 16 + erow] = sA;
            sred[w & 3][wm + mf * 16 + erow + 8] = sB;
        }
    }
    __syncthreads();
    if (tid < 128) {
        float s = sred[0][tid] + sred[1][tid] + sred[2][tid] + sred[3][tid];
        g_psum[(size_t)(m0 + tid) * NTILE + blockIdx.y] = s;
    }
}

// ------------------------- normalize (softmax finish) ----------------------
__global__ __launch_bounds__(256) void normalize_kernel(float* __restrict__ out) {
    __shared__ float sh[256];
    const int row = blockIdx.x, t = threadIdx.x;
    sh[t] = (t < NTILE) ? g_psum[(size_t)row * NTILE + t] : 0.f;
    __syncthreads();
    #pragma unroll
    for (int s = 128; s; s >>= 1) {
        if (t < s) sh[t] += sh[t + s];
        __syncthreads();
    }
    const float inv = 1.0f / sh[0];
    float4* o = (float4*)(out + (size_t)row * VV);
    for (int i = t; i < VV / 4; i += 256) {
        float4 v = o[i];
        v.x *= inv; v.y *= inv; v.z *= inv; v.w *= inv;
        o[i] = v;
    }
}

// ------------------------- launch ------------------------------------------
extern "C" void kernel_launch(void* const* d_in, const int* in_sizes, int n_in,
                              void* d_out, int out_size) {
    const int*   tokens = (const int*)d_in[0];
    const float* E  = (const float*)d_in[1];
    const float* Wi = (const float*)d_in[2];
    const float* bi = (const float*)d_in[3];
    const float* Wh = (const float*)d_in[4];
    const float* bh = (const float*)d_in[5];
    const float* Wo = (const float*)d_in[6];
    const float* bo = (const float*)d_in[7];
    float* out = (float*)d_out;

    cudaFuncSetAttribute(rnn_kernel, cudaFuncAttributeMaxDynamicSharedMemorySize, RNN_SMEM);

    static float *pPre0 = nullptr;
    static uint8_t *pE8, *pY8;
    if (!pPre0) {
        cudaGetSymbolAddress((void**)&pPre0, g_pre0);
        cudaGetSymbolAddress((void**)&pE8,   g_E8);
        cudaGetSymbolAddress((void**)&pY8,   g_Y8);
    }

    // 1: all prep (gather, transpose, biases, Wi/Wo1 bf16, E fp8)
    fused_prep<<<20736, 256>>>(tokens, E, Wi, bi, bh, Wo, bo);
    // 2: pre0 + M10 merged (192 CTAs, occ 2 -> one wave)
    aux_gemms<<<dim3(24, 8), 256>>>();
    // 3: recurrence (r14 structure, measured-best)
    rnn_kernel<<<NB_RNN, 256, RNN_SMEM>>>(Wh, pPre0);
    // 4: Y8 = fp8(x64)(HS1 @ Wo1.T + bo1)
    y_gemm<<<dim3(16, 8), 256>>>(bo + H);
    // 5: out = exp((Y8 @ E8^T)/4096), psum partials  (3-stage, 1 sync/iter)
    gemm_fp8_logits<<<dim3(16, NTILE), 256>>>(pY8, pE8, out);
    // 6: normalize rows
    normalize_kernel<<<MALL, 256>>>(out);
}